// round 13
// baseline (speedup 1.0000x reference)
#include <cuda_runtime.h>
#include <math.h>
#include <stdint.h>

#define B_    256
#define T_    64
#define MROWS (B_*T_)      // 16384
#define KDIM  753
#define KPAD  768          // F layout v2: [xemb(32), gemb(720), treat(1), pad(15)]
#define NDIM  640          // [a_pre(128), o_pre(128), gi(384)]
#define HID_  128

// ---- scratch (static device globals) ----
__device__ float2 g_F2[(size_t)MROWS * KPAD];   // (tf32_hi, tf32_lo) per element
__device__ float2 g_W2[(size_t)KPAD * NDIM];
__device__ float  g_O[(size_t)MROWS * NDIM];
__device__ float  g_da[B_ * HID_];
__device__ float  g_do[B_ * HID_];

__device__ __forceinline__ float eluf(float x) { return x > 0.f ? x : expm1f(x); }

__device__ __forceinline__ uint32_t f2tf32(float x) {
    uint32_t r; asm("cvt.rna.tf32.f32 %0, %1;" : "=r"(r) : "f"(x)); return r;
}
__device__ __forceinline__ float2 split_tf32(float v) {
    float hi = __uint_as_float(f2tf32(v));
    float lo = __uint_as_float(f2tf32(v - hi));
    return make_float2(hi, lo);
}

__device__ __forceinline__ void mma_tf32(float* c, const uint32_t* a, const uint32_t* b) {
    asm volatile(
        "mma.sync.aligned.m16n8k8.row.col.f32.tf32.tf32.f32 "
        "{%0,%1,%2,%3}, {%4,%5,%6,%7}, {%8,%9}, {%0,%1,%2,%3};"
        : "+f"(c[0]), "+f"(c[1]), "+f"(c[2]), "+f"(c[3])
        : "r"(a[0]), "r"(a[1]), "r"(a[2]), "r"(a[3]), "r"(b[0]), "r"(b[1]));
}

__device__ __forceinline__ void cp16(uint32_t saddr, const void* gaddr) {
    asm volatile("cp.async.cg.shared.global [%0], [%1], 16;\n" :: "r"(saddr), "l"(gaddr));
}
__device__ __forceinline__ void cp_commit() { asm volatile("cp.async.commit_group;\n"); }
template<int N> __device__ __forceinline__ void cp_wait() {
    asm volatile("cp.async.wait_group %0;\n" :: "n"(N));
}

// ============================================================
// Build fused weight matrix g_W2 (KPAD x NDIM), pre-split hi/lo.
// F layout v2: k<32 xemb | 32<=k<752 gemb(k-32) | k==752 treat | pad
// ============================================================
__global__ void build_w(const float* __restrict__ W_a1,
                        const float* __restrict__ W_o1,
                        const float* __restrict__ W_ih) {
    int idx = blockIdx.x * 256 + threadIdx.x;
    if (idx >= KPAD * NDIM) return;
    int k = idx / NDIM, c = idx % NDIM;
    float v;
    if (k >= KDIM) {
        v = 0.f;
    } else if (c < 128) {
        if (k < 32)        v = 0.f;
        else if (k == 752) v = 0.f;
        else               v = W_a1[c * 730 + 10 + (k - 32)];
    } else if (c < 256) {
        int co = c - 128;
        if (k < 32)        v = W_o1[co * 763 + k];
        else if (k == 752) v = W_o1[co * 763 + 42];
        else               v = W_o1[co * 763 + 43 + (k - 32)];
    } else {
        int r = c - 256;
        if (k < 32)        v = W_ih[r * 753 + k];
        else if (k == 752) v = W_ih[r * 753 + 32];
        else               v = W_ih[r * 753 + 33 + (k - 32)];
    }
    g_W2[idx] = split_tf32(v);
}

// ============================================================
// Per-batch demo precompute
// ============================================================
__global__ void demo_k(const float* __restrict__ x_demo,
                       const float* __restrict__ W_stat, const float* __restrict__ b_stat,
                       const float* __restrict__ W_a1,   const float* __restrict__ b_a1,
                       const float* __restrict__ W_o1,   const float* __restrict__ b_o1) {
    int b = blockIdx.x;
    int tid = threadIdx.x;
    __shared__ float d_sh[10];
    if (tid < 10) {
        float s = b_stat[tid];
        #pragma unroll
        for (int q = 0; q < 10; q++) s += x_demo[b * 10 + q] * W_stat[tid * 10 + q];
        d_sh[tid] = s;
    }
    __syncthreads();
    float sa = b_a1[tid], so = b_o1[tid];
    #pragma unroll
    for (int s = 0; s < 10; s++) {
        sa += d_sh[s] * W_a1[tid * 730 + s];
        so += d_sh[s] * W_o1[tid * 763 + 32 + s];
    }
    g_da[b * HID_ + tid] = sa;
    g_do[b * HID_ + tid] = so;
}

// ============================================================
// Feature kernel: per (b,t) build F row, split hi/lo at store time.
// Layout v2: [xemb(32), gemb(720), treat(1), pad(15)]
// ============================================================
__global__ void __launch_bounds__(128) feat_k(
    const float* __restrict__ x, const float* __restrict__ f_treat,
    const float* __restrict__ W_x2emb, const float* __restrict__ b_x2emb,
    const float* __restrict__ W_m1a, const float* __restrict__ b_m1a,
    const float* __restrict__ W_m1b, const float* __restrict__ b_m1b,
    const float* __restrict__ W_m2a, const float* __restrict__ b_m2a,
    const float* __restrict__ W_m2b, const float* __restrict__ b_m2b) {
    int m = blockIdx.x;
    int b = m >> 6, t = m & 63;
    int tid = threadIdx.x;

    __shared__ float h1s[80];
    __shared__ float w1a[32], w1b[64], w2a[128], w2b[64], wx[128];
    __shared__ float bx[32], bw1a[8], bw1b[8], bw2a[8], bw2b[8];

    w2a[tid] = W_m2a[tid];
    wx[tid]  = W_x2emb[tid];
    if (tid < 64) { w1b[tid] = W_m1b[tid]; w2b[tid] = W_m2b[tid]; }
    if (tid < 32) { w1a[tid] = W_m1a[tid]; bx[tid] = b_x2emb[tid]; }
    if (tid < 8)  { bw1a[tid] = b_m1a[tid]; bw1b[tid] = b_m1b[tid];
                    bw2a[tid] = b_m2a[tid]; bw2b[tid] = b_m2b[tid]; }
    __syncthreads();

    const float* xr = x + ((size_t)b * 65 + t) * 44;
    float2* Frow = g_F2 + (size_t)m * KPAD;

    if (tid < 10) {
        float xa[4];
        #pragma unroll
        for (int q = 0; q < 4; q++) xa[q] = xr[tid * 4 + q];
        float l1[8];
        #pragma unroll
        for (int j = 0; j < 8; j++) {
            float s = bw1a[j];
            #pragma unroll
            for (int q = 0; q < 4; q++) s += w1a[j * 4 + q] * xa[q];
            l1[j] = eluf(s);
        }
        #pragma unroll
        for (int j = 0; j < 8; j++) {
            float s = bw1b[j];
            #pragma unroll
            for (int q = 0; q < 8; q++) s += w1b[j * 8 + q] * l1[q];
            h1s[tid * 8 + j] = eluf(s);
        }
    } else if (tid >= 96) {
        int jj = tid - 96;
        float s = bx[jj];
        #pragma unroll
        for (int q = 0; q < 4; q++) s += wx[jj * 4 + q] * xr[40 + q];
        Frow[jj] = split_tf32(s);
    } else if (tid == 95) {
        Frow[752] = split_tf32(f_treat[(size_t)b * 65 + t]);
    } else if (tid >= 80 && tid < 95) {
        Frow[KDIM + (tid - 80)] = make_float2(0.f, 0.f);   // pad [753,768)
    }
    __syncthreads();

    if (tid < 90) {
        int e = tid;
        int i = e / 9, r = e % 9;
        int jn = (r < i) ? r : r + 1;
        float f[16];
        #pragma unroll
        for (int q = 0; q < 8; q++) { f[q] = h1s[i * 8 + q]; f[8 + q] = h1s[jn * 8 + q]; }
        float l1[8];
        #pragma unroll
        for (int j = 0; j < 8; j++) {
            float s = bw2a[j];
            #pragma unroll
            for (int q = 0; q < 16; q++) s += w2a[j * 16 + q] * f[q];
            l1[j] = eluf(s);
        }
        float4* dst = (float4*)(Frow + 32 + e * 8);   // 16B-aligned (index even)
        #pragma unroll
        for (int jp = 0; jp < 4; jp++) {
            float s0 = bw2b[jp * 2], s1 = bw2b[jp * 2 + 1];
            #pragma unroll
            for (int q = 0; q < 8; q++) {
                s0 += w2b[(jp * 2) * 8 + q] * l1[q];
                s1 += w2b[(jp * 2 + 1) * 8 + q] * l1[q];
            }
            float2 a = split_tf32(eluf(s0));
            float2 c = split_tf32(eluf(s1));
            dst[jp] = make_float4(a.x, a.y, c.x, c.y);
        }
    }
}

// ============================================================
// 3xTF32 GEMM, pre-split operands, LDS.64 (hi,lo) fragments.
// g_O (16384 x 640) = F (16384 x 768) @ W (768 x 640)
// 256 threads (2x4 warps), block tile 128x128, warp tile 64x32, BK=16.
// A smem stride 20 float2 (40 words: frag banks 8g+2tg bijective)
// B smem stride 132 float2 (264 words: frag banks 8tg+2g bijective)
// ============================================================
#define GBM 128
#define GBN 128
#define GBK 16
#define NKT (KPAD / GBK)   // 48
#define ASTR2 20
#define BSTR2 132
#define A_STAGE (GBM * ASTR2)          // float2 per stage
#define B_STAGE (GBK * BSTR2)
#define SMEM_BYTES (2 * (A_STAGE + B_STAGE) * 8)   // 74752

__global__ void __launch_bounds__(256, 2) gemm_tf32() {
    extern __shared__ float2 smem2[];
    float2* As2 = smem2;                       // [2][GBM][ASTR2]
    float2* Bs2 = smem2 + 2 * A_STAGE;         // [2][GBK][BSTR2]

    const int tid  = threadIdx.x;
    const int warp = tid >> 5, lane = tid & 31;
    const int g = lane >> 2, tg = lane & 3;
    const int wm = (warp & 1) * 64;
    const int wn = (warp >> 1) * 32;
    const int bm = blockIdx.y * GBM, bn = blockIdx.x * GBN;

    uint32_t sA = (uint32_t)__cvta_generic_to_shared(As2);
    uint32_t sB = (uint32_t)__cvta_generic_to_shared(Bs2);

    // cp.async mappings
    const int arow = tid >> 1;                 // 0..127
    const int acb  = (tid & 1) * 4;            // chunk base 0 or 4
    const int bkr  = tid >> 4;                 // 0..15
    const int bcb  = tid & 15;                 // chunk base

    float acc[4][4][4];
    #pragma unroll
    for (int i = 0; i < 4; i++)
        #pragma unroll
        for (int j = 0; j < 4; j++)
            #pragma unroll
            for (int q = 0; q < 4; q++) acc[i][j][q] = 0.f;

    auto load_tile = [&](int s, int kt) {
        const int k0 = kt * GBK;
        // A: 128 rows x 16 el (float2) = 1024 cp16; 4/thread
        const float2* asrc = g_F2 + (size_t)(bm + arow) * KPAD + k0;
        uint32_t adst = sA + (uint32_t)(s * A_STAGE + arow * ASTR2) * 8;
        #pragma unroll
        for (int p = 0; p < 4; p++)
            cp16(adst + (acb + p) * 16, asrc + (acb + p) * 2);
        // B: 16 rows x 128 el = 1024 cp16; 4/thread
        const float2* bsrc = g_W2 + (size_t)(k0 + bkr) * NDIM + bn;
        uint32_t bdst = sB + (uint32_t)(s * B_STAGE + bkr * BSTR2) * 8;
        #pragma unroll
        for (int p = 0; p < 4; p++)
            cp16(bdst + (bcb + p * 16) * 16, bsrc + (bcb + p * 16) * 2);
    };

    load_tile(0, 0); cp_commit();
    load_tile(1, 1); cp_commit();

    for (int kt = 0; kt < NKT; kt++) {
        cp_wait<1>();
        __syncthreads();
        const float2* Asb = As2 + (kt & 1) * A_STAGE;
        const float2* Bsb = Bs2 + (kt & 1) * B_STAGE;

        #pragma unroll
        for (int ks = 0; ks < 2; ks++) {
            const int kb = ks * 8;
            uint32_t a_h[4][4], a_l[4][4];
            #pragma unroll
            for (int mt = 0; mt < 4; mt++) {
                int mr = wm + mt * 16 + g;
                #pragma unroll
                for (int r = 0; r < 4; r++) {
                    float2 v = Asb[(mr + (r & 1) * 8) * ASTR2 + kb + tg + (r >> 1) * 4];
                    a_h[mt][r] = __float_as_uint(v.x);
                    a_l[mt][r] = __float_as_uint(v.y);
                }
            }
            #pragma unroll
            for (int nt = 0; nt < 4; nt++) {
                int nc = wn + nt * 8 + g;
                uint32_t b_h[2], b_l[2];
                #pragma unroll
                for (int r = 0; r < 2; r++) {
                    float2 v = Bsb[(kb + tg + r * 4) * BSTR2 + nc];
                    b_h[r] = __float_as_uint(v.x);
                    b_l[r] = __float_as_uint(v.y);
                }
                #pragma unroll
                for (int mt = 0; mt < 4; mt++) {
                    mma_tf32(acc[mt][nt], a_h[mt], b_h);
                    mma_tf32(acc[mt][nt], a_h[mt], b_l);
                    mma_tf32(acc[mt][nt], a_l[mt], b_h);
                }
            }
        }
        __syncthreads();
        if (kt + 2 < NKT) load_tile(kt & 1, kt + 2);
        cp_commit();
    }

    #pragma unroll
    for (int mt = 0; mt < 4; mt++) {
        #pragma unroll
        for (int nt = 0; nt < 4; nt++) {
            int row = bm + wm + mt * 16 + g;
            int col = bn + wn + nt * 8 + tg * 2;
            *(float2*)&g_O[(size_t)row * NDIM + col] =
                make_float2(acc[mt][nt][0], acc[mt][nt][1]);
            *(float2*)&g_O[(size_t)(row + 8) * NDIM + col] =
                make_float2(acc[mt][nt][2], acc[mt][nt][3]);
        }
    }
}

// ============================================================
// Head kernel
// ============================================================
__global__ void head_k(const float* __restrict__ W_a2, const float* __restrict__ W_o2,
                       float* __restrict__ out) {
    int m = blockIdx.x * 8 + threadIdx.y;
    int lane = threadIdx.x;
    int b = m >> 6;
    const float* row = g_O + (size_t)m * NDIM;
    float sa = 0.f, so = 0.f;
    #pragma unroll
    for (int q = 0; q < 4; q++) {
        int c = lane * 4 + q;
        float av = row[c] + g_da[b * HID_ + c];
        sa += fmaxf(av, 0.f) * W_a2[c];
        float ov = row[128 + c] + g_do[b * HID_ + c];
        so += fmaxf(ov, 0.f) * W_o2[c];
    }
    #pragma unroll
    for (int off = 16; off; off >>= 1) {
        sa += __shfl_down_sync(0xffffffffu, sa, off);
        so += __shfl_down_sync(0xffffffffu, so, off);
    }
    if (lane == 0) {
        out[(size_t)m * 130 + 0] = sa;
        out[(size_t)m * 130 + 1] = so;
    }
}

// ============================================================
// GRU scan: 1 block per batch sample, 384 threads, FFMA2 matvec.
// ============================================================
__global__ void __launch_bounds__(384, 1) gru_k(
    const float* __restrict__ h0, const float* __restrict__ W_hh,
    const float* __restrict__ b_hh, const float* __restrict__ b_ih,
    float* __restrict__ out) {
    int b = blockIdx.x;
    int j = threadIdx.x;

    __shared__ float h_sh[128];
    __shared__ float gh_sh[384];
    __shared__ float bih_sh[384];

    unsigned long long w2[64];
    #pragma unroll
    for (int q = 0; q < 64; q++)
        w2[q] = ((const unsigned long long*)(W_hh + (size_t)j * 128))[q];
    float bh = b_hh[j];
    bih_sh[j] = b_ih[j];
    if (j < 128) h_sh[j] = h0[b * 128 + j];
    __syncthreads();

    const unsigned long long* h2p = (const unsigned long long*)h_sh;

    for (int t = 0; t < T_; t++) {
        int m = b * T_ + t;
        unsigned long long acc2 = 0ull;
        #pragma unroll
        for (int q = 0; q < 64; q++) {
            asm("fma.rn.f32x2 %0, %1, %2, %0;"
                : "+l"(acc2) : "l"(w2[q]), "l"(h2p[q]));
        }
        uint32_t alo, ahi;
        asm("mov.b64 {%0,%1}, %2;" : "=r"(alo), "=r"(ahi) : "l"(acc2));
        gh_sh[j] = bh + __uint_as_float(alo) + __uint_as_float(ahi);
        __syncthreads();
        if (j < 128) {
            const float* gim = g_O + (size_t)m * NDIM + 256;
            float i_r = gim[j]       + bih_sh[j];
            float i_z = gim[128 + j] + bih_sh[128 + j];
            float i_n = gim[256 + j] + bih_sh[256 + j];
            float hr = gh_sh[j], hz = gh_sh[128 + j], hn = gh_sh[256 + j];
            float r = 1.f / (1.f + expf(-(i_r + hr)));
            float z = 1.f / (1.f + expf(-(i_z + hz)));
            float n = tanhf(i_n + r * hn);
            float h_new = (1.f - z) * n + z * h_sh[j];
            h_sh[j] = h_new;
            out[(size_t)m * 130 + 2 + j] = h_new;
        }
        __syncthreads();
    }
}

// ============================================================
extern "C" void kernel_launch(void* const* d_in, const int* in_sizes, int n_in,
                              void* d_out, int out_size) {
    const float* x        = (const float*)d_in[0];
    const float* x_demo   = (const float*)d_in[1];
    const float* f_treat  = (const float*)d_in[2];
    const float* h0       = (const float*)d_in[3];
    const float* W_x2emb  = (const float*)d_in[4];
    const float* b_x2emb  = (const float*)d_in[5];
    const float* W_stat   = (const float*)d_in[6];
    const float* b_stat   = (const float*)d_in[7];
    const float* W_m1a    = (const float*)d_in[8];
    const float* b_m1a    = (const float*)d_in[9];
    const float* W_m1b    = (const float*)d_in[10];
    const float* b_m1b    = (const float*)d_in[11];
    const float* W_m2a    = (const float*)d_in[12];
    const float* b_m2a    = (const float*)d_in[13];
    const float* W_m2b    = (const float*)d_in[14];
    const float* b_m2b    = (const float*)d_in[15];
    const float* W_a1     = (const float*)d_in[16];
    const float* b_a1     = (const float*)d_in[17];
    const float* W_a2     = (const float*)d_in[18];
    const float* W_o1     = (const float*)d_in[19];
    const float* b_o1     = (const float*)d_in[20];
    const float* W_o2     = (const float*)d_in[21];
    const float* W_ih     = (const float*)d_in[22];
    const float* b_ih     = (const float*)d_in[23];
    const float* W_hh     = (const float*)d_in[24];
    const float* b_hh     = (const float*)d_in[25];
    float* out = (float*)d_out;

    cudaFuncSetAttribute(gemm_tf32, cudaFuncAttributeMaxDynamicSharedMemorySize,
                         SMEM_BYTES);

    build_w<<<(KPAD * NDIM + 255) / 256, 256>>>(W_a1, W_o1, W_ih);
    demo_k<<<B_, 128>>>(x_demo, W_stat, b_stat, W_a1, b_a1, W_o1, b_o1);
    feat_k<<<MROWS, 128>>>(x, f_treat, W_x2emb, b_x2emb,
                           W_m1a, b_m1a, W_m1b, b_m1b,
                           W_m2a, b_m2a, W_m2b, b_m2b);
    dim3 gg(NDIM / GBN, MROWS / GBM);
    gemm_tf32<<<gg, 256, SMEM_BYTES>>>();
    head_k<<<MROWS / 8, dim3(32, 8)>>>(W_a2, W_o2, out);
    gru_k<<<B_, 384>>>(h0, W_hh, b_hh, b_ih, out);
}

// round 14
// speedup vs baseline: 1.2727x; 1.2727x over previous
#include <cuda_runtime.h>
#include <math.h>
#include <stdint.h>

#define B_    256
#define T_    64
#define MROWS (B_*T_)      // 16384
#define KDIM  753
#define KPAD  768          // F layout v2: [xemb(32), gemb(720), treat(1), pad(15)]
#define NDIM  640          // [a_pre(128), o_pre(128), gi(384)]
#define HID_  128

// ---- scratch (static device globals) ----
__device__ float  g_F[(size_t)MROWS * KPAD];    // raw fp32 features (~50MB)
__device__ float2 g_W2[(size_t)KPAD * NDIM];    // (tf32_hi, tf32_lo) weights
__device__ float  g_O[(size_t)MROWS * NDIM];
__device__ float  g_da[B_ * HID_];
__device__ float  g_do[B_ * HID_];

__device__ __forceinline__ float eluf(float x) { return x > 0.f ? x : expm1f(x); }

__device__ __forceinline__ uint32_t f2tf32(float x) {
    uint32_t r; asm("cvt.rna.tf32.f32 %0, %1;" : "=r"(r) : "f"(x)); return r;
}
__device__ __forceinline__ float2 split_tf32(float v) {
    float hi = __uint_as_float(f2tf32(v));
    float lo = __uint_as_float(f2tf32(v - hi));
    return make_float2(hi, lo);
}

__device__ __forceinline__ void mma_tf32(float* c, const uint32_t* a, const uint32_t* b) {
    asm volatile(
        "mma.sync.aligned.m16n8k8.row.col.f32.tf32.tf32.f32 "
        "{%0,%1,%2,%3}, {%4,%5,%6,%7}, {%8,%9}, {%0,%1,%2,%3};"
        : "+f"(c[0]), "+f"(c[1]), "+f"(c[2]), "+f"(c[3])
        : "r"(a[0]), "r"(a[1]), "r"(a[2]), "r"(a[3]), "r"(b[0]), "r"(b[1]));
}

__device__ __forceinline__ void cp16(uint32_t saddr, const void* gaddr) {
    asm volatile("cp.async.cg.shared.global [%0], [%1], 16;\n" :: "r"(saddr), "l"(gaddr));
}
__device__ __forceinline__ void cp_commit() { asm volatile("cp.async.commit_group;\n"); }
template<int N> __device__ __forceinline__ void cp_wait() {
    asm volatile("cp.async.wait_group %0;\n" :: "n"(N));
}

// ============================================================
// Build fused weight matrix g_W2 (KPAD x NDIM), pre-split hi/lo.
// F layout v2: k<32 xemb | 32<=k<752 gemb(k-32) | k==752 treat | pad
// ============================================================
__global__ void build_w(const float* __restrict__ W_a1,
                        const float* __restrict__ W_o1,
                        const float* __restrict__ W_ih) {
    int idx = blockIdx.x * 256 + threadIdx.x;
    if (idx >= KPAD * NDIM) return;
    int k = idx / NDIM, c = idx % NDIM;
    float v;
    if (k >= KDIM) {
        v = 0.f;
    } else if (c < 128) {
        if (k < 32)        v = 0.f;
        else if (k == 752) v = 0.f;
        else               v = W_a1[c * 730 + 10 + (k - 32)];
    } else if (c < 256) {
        int co = c - 128;
        if (k < 32)        v = W_o1[co * 763 + k];
        else if (k == 752) v = W_o1[co * 763 + 42];
        else               v = W_o1[co * 763 + 43 + (k - 32)];
    } else {
        int r = c - 256;
        if (k < 32)        v = W_ih[r * 753 + k];
        else if (k == 752) v = W_ih[r * 753 + 32];
        else               v = W_ih[r * 753 + 33 + (k - 32)];
    }
    g_W2[idx] = split_tf32(v);
}

// ============================================================
// Per-batch demo precompute
// ============================================================
__global__ void demo_k(const float* __restrict__ x_demo,
                       const float* __restrict__ W_stat, const float* __restrict__ b_stat,
                       const float* __restrict__ W_a1,   const float* __restrict__ b_a1,
                       const float* __restrict__ W_o1,   const float* __restrict__ b_o1) {
    int b = blockIdx.x;
    int tid = threadIdx.x;
    __shared__ float d_sh[10];
    if (tid < 10) {
        float s = b_stat[tid];
        #pragma unroll
        for (int q = 0; q < 10; q++) s += x_demo[b * 10 + q] * W_stat[tid * 10 + q];
        d_sh[tid] = s;
    }
    __syncthreads();
    float sa = b_a1[tid], so = b_o1[tid];
    #pragma unroll
    for (int s = 0; s < 10; s++) {
        sa += d_sh[s] * W_a1[tid * 730 + s];
        so += d_sh[s] * W_o1[tid * 763 + 32 + s];
    }
    g_da[b * HID_ + tid] = sa;
    g_do[b * HID_ + tid] = so;
}

// ============================================================
// Feature kernel: per (b,t) build raw fp32 F row (layout v2).
// ============================================================
__global__ void __launch_bounds__(128) feat_k(
    const float* __restrict__ x, const float* __restrict__ f_treat,
    const float* __restrict__ W_x2emb, const float* __restrict__ b_x2emb,
    const float* __restrict__ W_m1a, const float* __restrict__ b_m1a,
    const float* __restrict__ W_m1b, const float* __restrict__ b_m1b,
    const float* __restrict__ W_m2a, const float* __restrict__ b_m2a,
    const float* __restrict__ W_m2b, const float* __restrict__ b_m2b) {
    int m = blockIdx.x;
    int b = m >> 6, t = m & 63;
    int tid = threadIdx.x;

    __shared__ float h1s[80];
    __shared__ float w1a[32], w1b[64], w2a[128], w2b[64], wx[128];
    __shared__ float bx[32], bw1a[8], bw1b[8], bw2a[8], bw2b[8];

    w2a[tid] = W_m2a[tid];
    wx[tid]  = W_x2emb[tid];
    if (tid < 64) { w1b[tid] = W_m1b[tid]; w2b[tid] = W_m2b[tid]; }
    if (tid < 32) { w1a[tid] = W_m1a[tid]; bx[tid] = b_x2emb[tid]; }
    if (tid < 8)  { bw1a[tid] = b_m1a[tid]; bw1b[tid] = b_m1b[tid];
                    bw2a[tid] = b_m2a[tid]; bw2b[tid] = b_m2b[tid]; }
    __syncthreads();

    const float* xr = x + ((size_t)b * 65 + t) * 44;
    float* Frow = g_F + (size_t)m * KPAD;

    if (tid < 10) {
        float xa[4];
        #pragma unroll
        for (int q = 0; q < 4; q++) xa[q] = xr[tid * 4 + q];
        float l1[8];
        #pragma unroll
        for (int j = 0; j < 8; j++) {
            float s = bw1a[j];
            #pragma unroll
            for (int q = 0; q < 4; q++) s += w1a[j * 4 + q] * xa[q];
            l1[j] = eluf(s);
        }
        #pragma unroll
        for (int j = 0; j < 8; j++) {
            float s = bw1b[j];
            #pragma unroll
            for (int q = 0; q < 8; q++) s += w1b[j * 8 + q] * l1[q];
            h1s[tid * 8 + j] = eluf(s);
        }
    } else if (tid >= 96) {
        int jj = tid - 96;
        float s = bx[jj];
        #pragma unroll
        for (int q = 0; q < 4; q++) s += wx[jj * 4 + q] * xr[40 + q];
        Frow[jj] = s;
    } else if (tid == 95) {
        Frow[752] = f_treat[(size_t)b * 65 + t];
    } else if (tid >= 80 && tid < 95) {
        Frow[KDIM + (tid - 80)] = 0.f;   // pad [753,768)
    }
    __syncthreads();

    if (tid < 90) {
        int e = tid;
        int i = e / 9, r = e % 9;
        int jn = (r < i) ? r : r + 1;
        float f[16];
        #pragma unroll
        for (int q = 0; q < 8; q++) { f[q] = h1s[i * 8 + q]; f[8 + q] = h1s[jn * 8 + q]; }
        float l1[8];
        #pragma unroll
        for (int j = 0; j < 8; j++) {
            float s = bw2a[j];
            #pragma unroll
            for (int q = 0; q < 16; q++) s += w2a[j * 16 + q] * f[q];
            l1[j] = eluf(s);
        }
        float out8[8];
        #pragma unroll
        for (int j = 0; j < 8; j++) {
            float s = bw2b[j];
            #pragma unroll
            for (int q = 0; q < 8; q++) s += w2b[j * 8 + q] * l1[q];
            out8[j] = eluf(s);
        }
        float4* dst = (float4*)(Frow + 32 + e * 8);  // 16B-aligned
        dst[0] = make_float4(out8[0], out8[1], out8[2], out8[3]);
        dst[1] = make_float4(out8[4], out8[5], out8[6], out8[7]);
    }
}

// ============================================================
// 3xTF32 GEMM, hybrid: A raw fp32 (in-reg split), B pre-split (hi,lo).
// g_O (16384 x 640) = F (16384 x 768) @ W (768 x 640)
// 128 threads (2x2 warps), block tile 128x64, warp tile 64x32, BK=16.
// 3-stage cp.async. A smem stride 20 floats (banks 20g+tg bijective).
// B smem stride 68 float2 (136 words ≡ 8 mod 32: banks 8tg+2g bijective).
// ============================================================
#define GBM 128
#define GBN 64
#define GBK 16
#define NKT (KPAD / GBK)   // 48
#define STG 3
#define ASTR 20                       // floats per A row
#define BSTR2 68                      // float2 per B row
#define A_STAGE (GBM * ASTR)          // floats per stage (2560)
#define B_STAGE (GBK * BSTR2)         // float2 per stage (1088)
#define SMEM_BYTES (STG * (A_STAGE * 4 + B_STAGE * 8))   // 56832

__global__ void __launch_bounds__(128, 4) gemm_tf32() {
    extern __shared__ char smraw[];
    float*  As = (float*)smraw;                          // [STG][GBM][ASTR]
    float2* Bs = (float2*)(smraw + STG * A_STAGE * 4);   // [STG][GBK][BSTR2]

    const int tid  = threadIdx.x;
    const int warp = tid >> 5, lane = tid & 31;
    const int g = lane >> 2, tg = lane & 3;
    const int wm = (warp & 1) * 64;
    const int wn = (warp >> 1) * 32;
    const int bm = blockIdx.y * GBM, bn = blockIdx.x * GBN;

    uint32_t sA = (uint32_t)__cvta_generic_to_shared(As);
    uint32_t sB = (uint32_t)__cvta_generic_to_shared(Bs);

    // cp.async mappings
    const int arow = tid >> 2;            // 0..31 (+p*32)
    const int akc  = (tid & 3) * 4;       // float offset
    const int brow = tid >> 3;            // 0..15
    const int bcc  = tid & 7;             // chunk col (+p*8), chunk = 2 float2

    float acc[4][4][4];
    #pragma unroll
    for (int i = 0; i < 4; i++)
        #pragma unroll
        for (int j = 0; j < 4; j++)
            #pragma unroll
            for (int q = 0; q < 4; q++) acc[i][j][q] = 0.f;

    auto load_tile = [&](int s, int kt) {
        const int k0 = kt * GBK;
        // A: 128 rows x 16 floats = 512 cp16; 4/thread
        #pragma unroll
        for (int p = 0; p < 4; p++) {
            int m = arow + p * 32;
            cp16(sA + (uint32_t)((s * A_STAGE + m * ASTR + akc) * 4),
                 g_F + (size_t)(bm + m) * KPAD + k0 + akc);
        }
        // B: 16 rows x 64 float2 = 512 cp16 (2 float2 each); 4/thread
        #pragma unroll
        for (int p = 0; p < 4; p++) {
            int cc = bcc + p * 8;
            cp16(sB + (uint32_t)((s * B_STAGE + brow * BSTR2 + cc * 2) * 8),
                 g_W2 + (size_t)(k0 + brow) * NDIM + bn + cc * 2);
        }
    };

    load_tile(0, 0); cp_commit();
    load_tile(1, 1); cp_commit();

    for (int kt = 0; kt < NKT; kt++) {
        cp_wait<1>();
        __syncthreads();
        const int s = kt % STG;
        const float*  Asb = As + s * A_STAGE;
        const float2* Bsb = Bs + s * B_STAGE;

        #pragma unroll
        for (int ks = 0; ks < 2; ks++) {
            const int kb = ks * 8;
            uint32_t a_h[4][4], a_l[4][4];
            #pragma unroll
            for (int mt = 0; mt < 4; mt++) {
                int mr = wm + mt * 16 + g;
                #pragma unroll
                for (int r = 0; r < 4; r++) {
                    float raw = Asb[(mr + (r & 1) * 8) * ASTR + kb + tg + (r >> 1) * 4];
                    uint32_t hi = f2tf32(raw);
                    a_h[mt][r] = hi;
                    a_l[mt][r] = f2tf32(raw - __uint_as_float(hi));
                }
            }
            #pragma unroll
            for (int nt = 0; nt < 4; nt++) {
                int nc = wn + nt * 8 + g;
                uint32_t b_h[2], b_l[2];
                #pragma unroll
                for (int r = 0; r < 2; r++) {
                    float2 v = Bsb[(kb + tg + r * 4) * BSTR2 + nc];
                    b_h[r] = __float_as_uint(v.x);
                    b_l[r] = __float_as_uint(v.y);
                }
                #pragma unroll
                for (int mt = 0; mt < 4; mt++) {
                    mma_tf32(acc[mt][nt], a_h[mt], b_h);
                    mma_tf32(acc[mt][nt], a_h[mt], b_l);
                    mma_tf32(acc[mt][nt], a_l[mt], b_h);
                }
            }
        }
        __syncthreads();
        if (kt + 2 < NKT) load_tile((kt + 2) % STG, kt + 2);
        cp_commit();
    }

    #pragma unroll
    for (int mt = 0; mt < 4; mt++) {
        #pragma unroll
        for (int nt = 0; nt < 4; nt++) {
            int row = bm + wm + mt * 16 + g;
            int col = bn + wn + nt * 8 + tg * 2;
            *(float2*)&g_O[(size_t)row * NDIM + col] =
                make_float2(acc[mt][nt][0], acc[mt][nt][1]);
            *(float2*)&g_O[(size_t)(row + 8) * NDIM + col] =
                make_float2(acc[mt][nt][2], acc[mt][nt][3]);
        }
    }
}

// ============================================================
// Head kernel
// ============================================================
__global__ void head_k(const float* __restrict__ W_a2, const float* __restrict__ W_o2,
                       float* __restrict__ out) {
    int m = blockIdx.x * 8 + threadIdx.y;
    int lane = threadIdx.x;
    int b = m >> 6;
    const float* row = g_O + (size_t)m * NDIM;
    float sa = 0.f, so = 0.f;
    #pragma unroll
    for (int q = 0; q < 4; q++) {
        int c = lane * 4 + q;
        float av = row[c] + g_da[b * HID_ + c];
        sa += fmaxf(av, 0.f) * W_a2[c];
        float ov = row[128 + c] + g_do[b * HID_ + c];
        so += fmaxf(ov, 0.f) * W_o2[c];
    }
    #pragma unroll
    for (int off = 16; off; off >>= 1) {
        sa += __shfl_down_sync(0xffffffffu, sa, off);
        so += __shfl_down_sync(0xffffffffu, so, off);
    }
    if (lane == 0) {
        out[(size_t)m * 130 + 0] = sa;
        out[(size_t)m * 130 + 1] = so;
    }
}

// ============================================================
// GRU scan: 1 block per batch sample, 384 threads, FFMA2 matvec.
// ============================================================
__global__ void __launch_bounds__(384, 1) gru_k(
    const float* __restrict__ h0, const float* __restrict__ W_hh,
    const float* __restrict__ b_hh, const float* __restrict__ b_ih,
    float* __restrict__ out) {
    int b = blockIdx.x;
    int j = threadIdx.x;

    __shared__ float h_sh[128];
    __shared__ float gh_sh[384];
    __shared__ float bih_sh[384];

    unsigned long long w2[64];
    #pragma unroll
    for (int q = 0; q < 64; q++)
        w2[q] = ((const unsigned long long*)(W_hh + (size_t)j * 128))[q];
    float bh = b_hh[j];
    bih_sh[j] = b_ih[j];
    if (j < 128) h_sh[j] = h0[b * 128 + j];
    __syncthreads();

    const unsigned long long* h2p = (const unsigned long long*)h_sh;

    for (int t = 0; t < T_; t++) {
        int m = b * T_ + t;
        unsigned long long acc2 = 0ull;
        #pragma unroll
        for (int q = 0; q < 64; q++) {
            asm("fma.rn.f32x2 %0, %1, %2, %0;"
                : "+l"(acc2) : "l"(w2[q]), "l"(h2p[q]));
        }
        uint32_t alo, ahi;
        asm("mov.b64 {%0,%1}, %2;" : "=r"(alo), "=r"(ahi) : "l"(acc2));
        gh_sh[j] = bh + __uint_as_float(alo) + __uint_as_float(ahi);
        __syncthreads();
        if (j < 128) {
            const float* gim = g_O + (size_t)m * NDIM + 256;
            float i_r = gim[j]       + bih_sh[j];
            float i_z = gim[128 + j] + bih_sh[128 + j];
            float i_n = gim[256 + j] + bih_sh[256 + j];
            float hr = gh_sh[j], hz = gh_sh[128 + j], hn = gh_sh[256 + j];
            float r = 1.f / (1.f + expf(-(i_r + hr)));
            float z = 1.f / (1.f + expf(-(i_z + hz)));
            float n = tanhf(i_n + r * hn);
            float h_new = (1.f - z) * n + z * h_sh[j];
            h_sh[j] = h_new;
            out[(size_t)m * 130 + 2 + j] = h_new;
        }
        __syncthreads();
    }
}

// ============================================================
extern "C" void kernel_launch(void* const* d_in, const int* in_sizes, int n_in,
                              void* d_out, int out_size) {
    const float* x        = (const float*)d_in[0];
    const float* x_demo   = (const float*)d_in[1];
    const float* f_treat  = (const float*)d_in[2];
    const float* h0       = (const float*)d_in[3];
    const float* W_x2emb  = (const float*)d_in[4];
    const float* b_x2emb  = (const float*)d_in[5];
    const float* W_stat   = (const float*)d_in[6];
    const float* b_stat   = (const float*)d_in[7];
    const float* W_m1a    = (const float*)d_in[8];
    const float* b_m1a    = (const float*)d_in[9];
    const float* W_m1b    = (const float*)d_in[10];
    const float* b_m1b    = (const float*)d_in[11];
    const float* W_m2a    = (const float*)d_in[12];
    const float* b_m2a    = (const float*)d_in[13];
    const float* W_m2b    = (const float*)d_in[14];
    const float* b_m2b    = (const float*)d_in[15];
    const float* W_a1     = (const float*)d_in[16];
    const float* b_a1     = (const float*)d_in[17];
    const float* W_a2     = (const float*)d_in[18];
    const float* W_o1     = (const float*)d_in[19];
    const float* b_o1     = (const float*)d_in[20];
    const float* W_o2     = (const float*)d_in[21];
    const float* W_ih     = (const float*)d_in[22];
    const float* b_ih     = (const float*)d_in[23];
    const float* W_hh     = (const float*)d_in[24];
    const float* b_hh     = (const float*)d_in[25];
    float* out = (float*)d_out;

    cudaFuncSetAttribute(gemm_tf32, cudaFuncAttributeMaxDynamicSharedMemorySize,
                         SMEM_BYTES);

    build_w<<<(KPAD * NDIM + 255) / 256, 256>>>(W_a1, W_o1, W_ih);
    demo_k<<<B_, 128>>>(x_demo, W_stat, b_stat, W_a1, b_a1, W_o1, b_o1);
    feat_k<<<MROWS, 128>>>(x, f_treat, W_x2emb, b_x2emb,
                           W_m1a, b_m1a, W_m1b, b_m1b,
                           W_m2a, b_m2a, W_m2b, b_m2b);
    dim3 gg(NDIM / GBN, MROWS / GBM);
    gemm_tf32<<<gg, 128, SMEM_BYTES>>>();
    head_k<<<MROWS / 8, dim3(32, 8)>>>(W_a2, W_o2, out);
    gru_k<<<B_, 384>>>(h0, W_hh, b_hh, b_ih, out);
}